// round 10
// baseline (speedup 1.0000x reference)
#include <cuda_runtime.h>
#include <cuda_bf16.h>
#include <cstdint>

#define NLV 127.0f

// ---------------- scratch (__device__ globals) -------------------------------
__device__ float g_maxes[8];                       // 0:x 1:w1 2:w2 3:w3 4:h1 5:h2
__device__ __nv_bfloat16 g_xq[512 * 9216];
__device__ __nv_bfloat16 g_w1q_lo[4096 * 4608];    // w1 K-half 0 (cols 0..4607)
__device__ __nv_bfloat16 g_w1q_hi[4096 * 4608];    // w1 K-half 1
__device__ __nv_bfloat16 g_w2q[4096 * 4096];
__device__ __nv_bfloat16 g_w3q[1024 * 4096];       // padded 1000 -> 1024 rows
__device__ float g_h[512 * 4096];
__device__ __nv_bfloat16 g_hq[512 * 4096];
__device__ float g_part[4 * 512 * 1024];           // partials (GEMM1-K1 / GEMM3)

// ---------------- helpers ----------------------------------------------------
__device__ __forceinline__ uint32_t smem_u32(const void* p) {
    uint32_t a;
    asm("{ .reg .u64 t; cvta.to.shared.u64 t, %1; cvt.u32.u64 %0, t; }"
        : "=r"(a) : "l"(p));
    return a;
}

__device__ __forceinline__ void cp_async16(uint32_t saddr, const void* g) {
    asm volatile("cp.async.cg.shared.global [%0], [%1], 16;"
                 :: "r"(saddr), "l"(g) : "memory");
}

#define CP_COMMIT() asm volatile("cp.async.commit_group;" ::: "memory")

#define LDSM4(R, addr)                                                          \
    asm volatile("ldmatrix.sync.aligned.m8n8.x4.shared.b16 "                    \
                 "{%0, %1, %2, %3}, [%4];"                                      \
                 : "=r"((R)[0]), "=r"((R)[1]), "=r"((R)[2]), "=r"((R)[3])       \
                 : "r"(addr))

#define MMA16816(C, A, B0, B1)                                                  \
    asm volatile("mma.sync.aligned.m16n8k16.row.col.f32.bf16.bf16.f32 "         \
                 "{%0, %1, %2, %3}, {%4, %5, %6, %7}, {%8, %9}, "               \
                 "{%0, %1, %2, %3};"                                            \
                 : "+f"((C)[0]), "+f"((C)[1]), "+f"((C)[2]), "+f"((C)[3])       \
                 : "r"((A)[0]), "r"((A)[1]), "r"((A)[2]), "r"((A)[3]),          \
                   "r"(B0), "r"(B1))

// ---------------- small kernels ----------------------------------------------
__global__ void init_maxes_kernel() {
    if (threadIdx.x < 8) g_maxes[threadIdx.x] = 0.0f;
}

__global__ void maxabs_kernel(const float* __restrict__ src, int n4, int slot) {
    float m = 0.0f;
    const float4* s4 = (const float4*)src;
    for (int i = blockIdx.x * blockDim.x + threadIdx.x; i < n4;
         i += gridDim.x * blockDim.x) {
        float4 v = s4[i];
        m = fmaxf(m, fmaxf(fmaxf(fabsf(v.x), fabsf(v.y)),
                           fmaxf(fabsf(v.z), fabsf(v.w))));
    }
#pragma unroll
    for (int o = 16; o; o >>= 1) m = fmaxf(m, __shfl_xor_sync(0xFFFFFFFFu, m, o));
    __shared__ float sm[8];
    if ((threadIdx.x & 31) == 0) sm[threadIdx.x >> 5] = m;
    __syncthreads();
    if (threadIdx.x == 0) {
        float mm = sm[0];
#pragma unroll
        for (int w = 1; w < 8; w++) mm = fmaxf(mm, sm[w]);
        atomicMax((unsigned int*)&g_maxes[slot], __float_as_uint(mm));
    }
}

__device__ __forceinline__ uint32_t pack_bf16x2(float a, float b) {
    uint32_t lo = (uint32_t)__bfloat16_as_ushort(__float2bfloat16_rn(a));
    uint32_t hi = (uint32_t)__bfloat16_as_ushort(__float2bfloat16_rn(b));
    return lo | (hi << 16);
}

// quantize fp32 -> integer-valued bf16 (round-half-even, clip [lo,127])
__global__ void quant_kernel(const float* __restrict__ src,
                             __nv_bfloat16* __restrict__ dst,
                             int n4, int npad4, int slot, float lo) {
    float mx = g_maxes[slot];
    float scale = mx / NLV;
    if (!(scale > 0.0f)) scale = 1.0f;
    float inv = 1.0f / scale;
    for (int i = blockIdx.x * blockDim.x + threadIdx.x; i < npad4;
         i += gridDim.x * blockDim.x) {
        uint32_t w0 = 0u, w1 = 0u;
        if (i < n4) {
            float4 v = ((const float4*)src)[i];
            float q0 = fminf(fmaxf(rintf(v.x * inv), lo), NLV);
            float q1 = fminf(fmaxf(rintf(v.y * inv), lo), NLV);
            float q2 = fminf(fmaxf(rintf(v.z * inv), lo), NLV);
            float q3 = fminf(fmaxf(rintf(v.w * inv), lo), NLV);
            w0 = pack_bf16x2(q0, q1);
            w1 = pack_bf16x2(q2, q3);
        }
        ((uint2*)dst)[i] = make_uint2(w0, w1);
    }
}

// quantize one K-half of a row-major [rows, K4*4] fp32 matrix into a
// contiguous [rows, hc4*4] bf16 matrix. Reads are hc4*16-byte contiguous runs.
__global__ void quant_half_kernel(const float* __restrict__ src,
                                  __nv_bfloat16* __restrict__ dst,
                                  int rows, int K4, int hc4, int half,
                                  int slot) {
    float mx = g_maxes[slot];
    float scale = mx / NLV;
    if (!(scale > 0.0f)) scale = 1.0f;
    float inv = 1.0f / scale;
    int n = rows * hc4;
    for (int i = blockIdx.x * blockDim.x + threadIdx.x; i < n;
         i += gridDim.x * blockDim.x) {
        int row = i / hc4;
        int c4 = i - row * hc4;
        float4 v = ((const float4*)src)[(size_t)row * K4 + half * hc4 + c4];
        float q0 = fminf(fmaxf(rintf(v.x * inv), -NLV), NLV);
        float q1 = fminf(fmaxf(rintf(v.y * inv), -NLV), NLV);
        float q2 = fminf(fmaxf(rintf(v.z * inv), -NLV), NLV);
        float q3 = fminf(fmaxf(rintf(v.w * inv), -NLV), NLV);
        ((uint2*)dst)[i] = make_uint2(pack_bf16x2(q0, q1), pack_bf16x2(q2, q3));
    }
}

// split-K reduce for layer 3: sum 4 partials (fixed order), dequant + bias
__global__ void reduce3_kernel(const float* __restrict__ bias,
                               float* __restrict__ out) {
    int idx = blockIdx.x * blockDim.x + threadIdx.x;   // over 512*500 float2
    if (idx >= 512 * 500) return;
    int m = idx / 500;
    int n = (idx % 500) * 2;
    const float* p = g_part + m * 1024 + n;
    float s0 = 0.0f, s1 = 0.0f;
#pragma unroll
    for (int k = 0; k < 4; k++) {
        float2 v = *(const float2*)(p + k * (512 * 1024));
        s0 += v.x;
        s1 += v.y;
    }
    const float bs = (g_maxes[5] / NLV) * (g_maxes[3] / NLV);
    float o0 = s0 * bs + rintf(bias[n] / bs) * bs;
    float o1 = s1 * bs + rintf(bias[n + 1] / bs) * bs;
    *(float2*)(out + (size_t)m * 1000 + n) = make_float2(o0, o1);
}

// ---------------- HMMA GEMM ----------------------------------------------------
// C[M=512, Nout] = A[512, KA-stride] (cols ka_ofs..) @ B[Npad, KB-stride]^T.
// Tile 128x128x64, 3-stage cp.async pipeline, 8 warps (64x32 warp tiles).
// raw=1: write unscaled partials. acc_in: fixed-order add of prior partial.
constexpr int BM = 128, BN = 128, BK = 64, STAGES = 3, NTHREADS = 256;
constexpr int STAGE_BYTES = (BM * BK + BN * BK) * 2;   // 32768
constexpr int B_OFS = BM * BK * 2;                     // 16384

__global__ void __launch_bounds__(NTHREADS, 1)
gemm_q_kernel(const __nv_bfloat16* __restrict__ A, int KA, int ka_ofs,
              const __nv_bfloat16* __restrict__ B, int KB,
              const float* __restrict__ bias, float* __restrict__ out,
              const float* __restrict__ acc_in,
              int Nout, int relu, int maxslot, int sa_slot, int sw_slot,
              int NK, int raw, int ostride) {
    extern __shared__ char smem_raw[];
    const uint32_t sb = smem_u32(smem_raw);

    const int tid = threadIdx.x;
    const int lane = tid & 31;
    const int wid = tid >> 5;
    const int wm = wid & 1;        // 2 m-blocks of 64
    const int wn = wid >> 1;       // 4 n-blocks of 32
    const int m0 = blockIdx.y * BM;
    const int n0 = blockIdx.x * BN;
    const size_t zofs = (size_t)blockIdx.z * NK * BK;
    float* outp = raw ? (out + (size_t)blockIdx.z * (512 * 1024)) : out;

    // ---- global->shared mapping: 2048 x 16B chunks / 256 threads = 8 each ----
    uint32_t s_st[8];
    const __nv_bfloat16* g_st[8];
#pragma unroll
    for (int i = 0; i < 8; i++) {
        int li = i * NTHREADS + tid;
        int isA = (li < 1024);
        int idx = li & 1023;
        int row = idx >> 3;            // 0..127
        int c = idx & 7;               // 16B chunk within 128B row
        s_st[i] = (uint32_t)((isA ? 0 : B_OFS) + row * 128 +
                             ((c ^ (row & 7)) << 4));
        g_st[i] = (isA ? (A + (size_t)(m0 + row) * KA + ka_ofs)
                       : (B + (size_t)(n0 + row) * KB)) + zofs + c * 8;
    }

    // prologue loads
#pragma unroll
    for (int st = 0; st < 2; st++) {
        if (st < NK) {
            uint32_t base = sb + (uint32_t)(st % STAGES) * STAGE_BYTES;
#pragma unroll
            for (int i = 0; i < 8; i++)
                cp_async16(base + s_st[i], g_st[i] + (size_t)st * BK);
            CP_COMMIT();
        }
    }

    // ---- ldmatrix per-lane base addresses (within stage) ----
    const int r = lane & 7;
    const int g = lane >> 3;
    uint32_t a_row[4];
    int a_rx[4];
#pragma unroll
    for (int mi = 0; mi < 4; mi++) {
        int row = wm * 64 + mi * 16 + (g & 1) * 8 + r;
        a_row[mi] = (uint32_t)(row * 128);
        a_rx[mi] = row & 7;
    }
    uint32_t b_row[2];
    int b_rx[2];
#pragma unroll
    for (int p = 0; p < 2; p++) {
        int row = wn * 32 + p * 16 + (g >> 1) * 8 + r;
        b_row[p] = (uint32_t)(B_OFS + row * 128);
        b_rx[p] = row & 7;
    }

    float acc[4][4][4];
#pragma unroll
    for (int mi = 0; mi < 4; mi++)
#pragma unroll
        for (int ni = 0; ni < 4; ni++)
#pragma unroll
            for (int e = 0; e < 4; e++) acc[mi][ni][e] = 0.0f;

#pragma unroll 1
    for (int kc = 0; kc < NK; kc++) {
        if (kc + 2 < NK) {
            uint32_t base = sb + (uint32_t)((kc + 2) % STAGES) * STAGE_BYTES;
#pragma unroll
            for (int i = 0; i < 8; i++)
                cp_async16(base + s_st[i], g_st[i] + (size_t)(kc + 2) * BK);
            CP_COMMIT();
        }
        int rem = NK - 1 - kc;
        if (rem >= 2)      asm volatile("cp.async.wait_group 2;" ::: "memory");
        else if (rem == 1) asm volatile("cp.async.wait_group 1;" ::: "memory");
        else               asm volatile("cp.async.wait_group 0;" ::: "memory");
        __syncthreads();

        const uint32_t stage = sb + (uint32_t)(kc % STAGES) * STAGE_BYTES;
#pragma unroll
        for (int s = 0; s < 4; s++) {
            uint32_t af[4][4];
#pragma unroll
            for (int mi = 0; mi < 4; mi++) {
                int chunk = 2 * s + (g >> 1);
                LDSM4(af[mi], stage + a_row[mi] +
                              (uint32_t)((chunk ^ a_rx[mi]) << 4));
            }
            uint32_t bf[2][4];
#pragma unroll
            for (int p = 0; p < 2; p++) {
                int chunk = 2 * s + (g & 1);
                LDSM4(bf[p], stage + b_row[p] +
                             (uint32_t)((chunk ^ b_rx[p]) << 4));
            }
#pragma unroll
            for (int mi = 0; mi < 4; mi++) {
#pragma unroll
                for (int p = 0; p < 2; p++) {
                    MMA16816(acc[mi][2 * p],     af[mi], bf[p][0], bf[p][1]);
                    MMA16816(acc[mi][2 * p + 1], af[mi], bf[p][2], bf[p][3]);
                }
            }
        }
        __syncthreads();
    }

    // ---- epilogue ----
    if (raw) {
#pragma unroll
        for (int mi = 0; mi < 4; mi++) {
#pragma unroll
            for (int half = 0; half < 2; half++) {
                int m = m0 + wm * 64 + mi * 16 + (lane >> 2) + half * 8;
#pragma unroll
                for (int ni = 0; ni < 4; ni++) {
                    int n = n0 + wn * 32 + ni * 8 + (lane & 3) * 2;
                    *(float2*)(outp + (size_t)m * ostride + n) =
                        make_float2(acc[mi][ni][half * 2 + 0],
                                    acc[mi][ni][half * 2 + 1]);
                }
            }
        }
        return;
    }

    const float sa = g_maxes[sa_slot] / NLV;
    const float sw = g_maxes[sw_slot] / NLV;
    const float bs = sa * sw;
    float lmax = 0.0f;

    float bq[4][2];
#pragma unroll
    for (int ni = 0; ni < 4; ni++) {
        int n = n0 + wn * 32 + ni * 8 + (lane & 3) * 2;
#pragma unroll
        for (int e = 0; e < 2; e++)
            bq[ni][e] = (n + e < Nout) ? rintf(bias[n + e] / bs) * bs : 0.0f;
    }

#pragma unroll
    for (int mi = 0; mi < 4; mi++) {
#pragma unroll
        for (int half = 0; half < 2; half++) {
            int m = m0 + wm * 64 + mi * 16 + (lane >> 2) + half * 8;
#pragma unroll
            for (int ni = 0; ni < 4; ni++) {
                int n = n0 + wn * 32 + ni * 8 + (lane & 3) * 2;
                if (n < Nout) {
                    float a0 = acc[mi][ni][half * 2 + 0];
                    float a1 = acc[mi][ni][half * 2 + 1];
                    if (acc_in) {
                        float2 pv = *(const float2*)(acc_in +
                                                     (size_t)m * ostride + n);
                        a0 += pv.x;
                        a1 += pv.y;
                    }
                    float v0 = a0 * bs + bq[ni][0];
                    float v1 = a1 * bs + bq[ni][1];
                    if (relu) { v0 = fmaxf(v0, 0.0f); v1 = fmaxf(v1, 0.0f); }
                    *(float2*)(outp + (size_t)m * ostride + n) =
                        make_float2(v0, v1);
                    lmax = fmaxf(lmax, fmaxf(fabsf(v0), fabsf(v1)));
                }
            }
        }
    }
    if (maxslot >= 0) {
#pragma unroll
        for (int o = 16; o; o >>= 1)
            lmax = fmaxf(lmax, __shfl_xor_sync(0xFFFFFFFFu, lmax, o));
        if (lane == 0)
            atomicMax((unsigned int*)&g_maxes[maxslot], __float_as_uint(lmax));
    }
}

// ---------------- launch -------------------------------------------------------
extern "C" void kernel_launch(void* const* d_in, const int* in_sizes, int n_in,
                              void* d_out, int out_size) {
    const float* x  = (const float*)d_in[0];
    const float* w1 = (const float*)d_in[1];
    const float* b1 = (const float*)d_in[2];
    const float* w2 = (const float*)d_in[3];
    const float* b2 = (const float*)d_in[4];
    const float* w3 = (const float*)d_in[5];
    const float* b3 = (const float*)d_in[6];
    float* out = (float*)d_out;

    void *p_xq, *p_w1lo, *p_w1hi, *p_w2q, *p_w3q, *p_h, *p_hq, *p_part;
    cudaGetSymbolAddress(&p_xq, g_xq);
    cudaGetSymbolAddress(&p_w1lo, g_w1q_lo);
    cudaGetSymbolAddress(&p_w1hi, g_w1q_hi);
    cudaGetSymbolAddress(&p_w2q, g_w2q);
    cudaGetSymbolAddress(&p_w3q, g_w3q);
    cudaGetSymbolAddress(&p_h, g_h);
    cudaGetSymbolAddress(&p_hq, g_hq);
    cudaGetSymbolAddress(&p_part, g_part);

    const int SMEM = STAGES * STAGE_BYTES;   // 98304
    cudaFuncSetAttribute(gemm_q_kernel,
                         cudaFuncAttributeMaxDynamicSharedMemorySize, SMEM);

    const int RB = 1184;  // 8 * 148 SMs, grid-stride

    cudaStream_t s1;
    cudaStreamCreateWithFlags(&s1, cudaStreamNonBlocking);
    cudaEvent_t e_lo, e_hi, e_aux;
    cudaEventCreateWithFlags(&e_lo, cudaEventDisableTiming);
    cudaEventCreateWithFlags(&e_hi, cudaEventDisableTiming);
    cudaEventCreateWithFlags(&e_aux, cudaEventDisableTiming);

    init_maxes_kernel<<<1, 32>>>();

    // x aux (L2-paired)
    maxabs_kernel<<<RB, 256>>>(x,  (512 * 9216) / 4, 0);
    quant_kernel<<<RB, 256>>>(x,  (__nv_bfloat16*)p_xq,
                              (512 * 9216) / 4, (512 * 9216) / 4, 0, -128.0f);

    // w1 aux: full maxabs, then lo-half quant on the critical path
    maxabs_kernel<<<RB, 256>>>(w1, (4096 * 9216) / 4, 1);
    quant_half_kernel<<<RB, 256>>>(w1, (__nv_bfloat16*)p_w1lo,
                                   4096, 9216 / 4, 4608 / 4, 0, 1);
    cudaEventRecord(e_lo, 0);

    // s1: hi-half quant (under GEMM1-K1), then w2/w3 aux
    cudaStreamWaitEvent(s1, e_lo, 0);
    quant_half_kernel<<<RB, 256, 0, s1>>>(w1, (__nv_bfloat16*)p_w1hi,
                                          4096, 9216 / 4, 4608 / 4, 1, 1);
    cudaEventRecord(e_hi, s1);
    maxabs_kernel<<<RB, 256, 0, s1>>>(w2, (4096 * 4096) / 4, 2);
    quant_kernel<<<RB, 256, 0, s1>>>(w2, (__nv_bfloat16*)p_w2q,
                                     (4096 * 4096) / 4, (4096 * 4096) / 4, 2,
                                     -127.0f);
    maxabs_kernel<<<RB, 256, 0, s1>>>(w3, (1000 * 4096) / 4, 3);
    quant_kernel<<<RB, 256, 0, s1>>>(w3, (__nv_bfloat16*)p_w3q,
                                     (1000 * 4096) / 4, (1024 * 4096) / 4, 3,
                                     -127.0f);
    cudaEventRecord(e_aux, s1);

    // GEMM1-K1: first K-half -> raw partials in g_part (concurrent with s1)
    gemm_q_kernel<<<dim3(32, 4, 1), NTHREADS, SMEM>>>(
        (const __nv_bfloat16*)p_xq, 9216, 0,
        (const __nv_bfloat16*)p_w1lo, 4608,
        b1, (float*)p_part, nullptr,
        4096, 0, -1, 0, 1, 4608 / 64, 1, 4096);

    // GEMM1-K2: second K-half + partial add + epilogue (needs w1q_hi)
    cudaStreamWaitEvent(0, e_hi, 0);
    gemm_q_kernel<<<dim3(32, 4, 1), NTHREADS, SMEM>>>(
        (const __nv_bfloat16*)p_xq, 9216, 4608,
        (const __nv_bfloat16*)p_w1hi, 4608,
        b1, (float*)p_h, (const float*)p_part,
        4096, 1, 4, 0, 1, 4608 / 64, 0, 4096);
    quant_kernel<<<RB, 256>>>((const float*)p_h, (__nv_bfloat16*)p_hq,
                              (512 * 4096) / 4, (512 * 4096) / 4, 4, -128.0f);

    // GEMM2 needs w2q (and downstream GEMM3 needs w3q)
    cudaStreamWaitEvent(0, e_aux, 0);
    gemm_q_kernel<<<dim3(32, 4, 1), NTHREADS, SMEM>>>(
        (const __nv_bfloat16*)p_hq, 4096, 0,
        (const __nv_bfloat16*)p_w2q, 4096,
        b2, (float*)p_h, nullptr,
        4096, 1, 5, 4, 2, 4096 / 64, 0, 4096);
    quant_kernel<<<RB, 256>>>((const float*)p_h, (__nv_bfloat16*)p_hq,
                              (512 * 4096) / 4, (512 * 4096) / 4, 5, -128.0f);

    // Layer 3: split-K=4 raw partials (8x4x4 = 128 CTAs), then reduce
    gemm_q_kernel<<<dim3(8, 4, 4), NTHREADS, SMEM>>>(
        (const __nv_bfloat16*)p_hq, 4096, 0,
        (const __nv_bfloat16*)p_w3q, 4096,
        b3, (float*)p_part, nullptr,
        1024, 0, -1, 5, 3, (4096 / 64) / 4, 1, 1024);
    reduce3_kernel<<<(512 * 500 + 255) / 256, 256>>>(b3, out);

    cudaEventDestroy(e_lo);
    cudaEventDestroy(e_hi);
    cudaEventDestroy(e_aux);
    cudaStreamDestroy(s1);
}

// round 11
// speedup vs baseline: 1.0955x; 1.0955x over previous
#include <cuda_runtime.h>
#include <cuda_bf16.h>
#include <cstdint>

#define NLV 127.0f

// ---------------- scratch (__device__ globals) -------------------------------
__device__ float g_maxes[8];                       // 0:x 1:w1 2:w2 3:w3 4:h1 5:h2
__device__ __nv_bfloat16 g_xq[512 * 9216];
__device__ __nv_bfloat16 g_w1q[4096 * 9216];
__device__ __nv_bfloat16 g_w2q[4096 * 4096];
__device__ __nv_bfloat16 g_w3q[1024 * 4096];       // padded 1000 -> 1024 rows
__device__ float g_h[512 * 4096];
__device__ __nv_bfloat16 g_hq[512 * 4096];
__device__ float g_part[4 * 512 * 1024];           // split-K partials for layer 3

// ---------------- helpers ----------------------------------------------------
__device__ __forceinline__ uint32_t smem_u32(const void* p) {
    uint32_t a;
    asm("{ .reg .u64 t; cvta.to.shared.u64 t, %1; cvt.u32.u64 %0, t; }"
        : "=r"(a) : "l"(p));
    return a;
}

__device__ __forceinline__ void cp_async16(uint32_t saddr, const void* g) {
    asm volatile("cp.async.cg.shared.global [%0], [%1], 16;"
                 :: "r"(saddr), "l"(g) : "memory");
}

#define CP_COMMIT() asm volatile("cp.async.commit_group;" ::: "memory")

#define LDSM4(R, addr)                                                          \
    asm volatile("ldmatrix.sync.aligned.m8n8.x4.shared.b16 "                    \
                 "{%0, %1, %2, %3}, [%4];"                                      \
                 : "=r"((R)[0]), "=r"((R)[1]), "=r"((R)[2]), "=r"((R)[3])       \
                 : "r"(addr))

#define MMA16816(C, A, B0, B1)                                                  \
    asm volatile("mma.sync.aligned.m16n8k16.row.col.f32.bf16.bf16.f32 "         \
                 "{%0, %1, %2, %3}, {%4, %5, %6, %7}, {%8, %9}, "               \
                 "{%0, %1, %2, %3};"                                            \
                 : "+f"((C)[0]), "+f"((C)[1]), "+f"((C)[2]), "+f"((C)[3])       \
                 : "r"((A)[0]), "r"((A)[1]), "r"((A)[2]), "r"((A)[3]),          \
                   "r"(B0), "r"(B1))

// ---------------- small kernels ----------------------------------------------
__global__ void init_maxes_kernel() {
    if (threadIdx.x < 8) g_maxes[threadIdx.x] = 0.0f;
}

__global__ void maxabs_kernel(const float* __restrict__ src, int n4, int slot) {
    float m = 0.0f;
    const float4* s4 = (const float4*)src;
    for (int i = blockIdx.x * blockDim.x + threadIdx.x; i < n4;
         i += gridDim.x * blockDim.x) {
        float4 v = s4[i];
        m = fmaxf(m, fmaxf(fmaxf(fabsf(v.x), fabsf(v.y)),
                           fmaxf(fabsf(v.z), fabsf(v.w))));
    }
#pragma unroll
    for (int o = 16; o; o >>= 1) m = fmaxf(m, __shfl_xor_sync(0xFFFFFFFFu, m, o));
    __shared__ float sm[8];
    if ((threadIdx.x & 31) == 0) sm[threadIdx.x >> 5] = m;
    __syncthreads();
    if (threadIdx.x == 0) {
        float mm = sm[0];
#pragma unroll
        for (int w = 1; w < 8; w++) mm = fmaxf(mm, sm[w]);
        atomicMax((unsigned int*)&g_maxes[slot], __float_as_uint(mm));
    }
}

__device__ __forceinline__ uint32_t pack_bf16x2(float a, float b) {
    uint32_t lo = (uint32_t)__bfloat16_as_ushort(__float2bfloat16_rn(a));
    uint32_t hi = (uint32_t)__bfloat16_as_ushort(__float2bfloat16_rn(b));
    return lo | (hi << 16);
}

// quantize fp32 -> integer-valued bf16 (round-half-even, clip [lo,127])
__global__ void quant_kernel(const float* __restrict__ src,
                             __nv_bfloat16* __restrict__ dst,
                             int n4, int npad4, int slot, float lo) {
    float mx = g_maxes[slot];
    float scale = mx / NLV;
    if (!(scale > 0.0f)) scale = 1.0f;
    float inv = 1.0f / scale;
    for (int i = blockIdx.x * blockDim.x + threadIdx.x; i < npad4;
         i += gridDim.x * blockDim.x) {
        uint32_t w0 = 0u, w1 = 0u;
        if (i < n4) {
            float4 v = ((const float4*)src)[i];
            float q0 = fminf(fmaxf(rintf(v.x * inv), lo), NLV);
            float q1 = fminf(fmaxf(rintf(v.y * inv), lo), NLV);
            float q2 = fminf(fmaxf(rintf(v.z * inv), lo), NLV);
            float q3 = fminf(fmaxf(rintf(v.w * inv), lo), NLV);
            w0 = pack_bf16x2(q0, q1);
            w1 = pack_bf16x2(q2, q3);
        }
        ((uint2*)dst)[i] = make_uint2(w0, w1);
    }
}

// split-K reduce for layer 3: sum 4 partials (fixed order), dequant + bias
__global__ void reduce3_kernel(const float* __restrict__ bias,
                               float* __restrict__ out) {
    int idx = blockIdx.x * blockDim.x + threadIdx.x;   // over 512*500 float2
    if (idx >= 512 * 500) return;
    int m = idx / 500;
    int n = (idx % 500) * 2;
    const float* p = g_part + m * 1024 + n;
    float s0 = 0.0f, s1 = 0.0f;
#pragma unroll
    for (int k = 0; k < 4; k++) {
        float2 v = *(const float2*)(p + k * (512 * 1024));
        s0 += v.x;
        s1 += v.y;
    }
    const float bs = (g_maxes[5] / NLV) * (g_maxes[3] / NLV);
    float o0 = s0 * bs + rintf(bias[n] / bs) * bs;
    float o1 = s1 * bs + rintf(bias[n + 1] / bs) * bs;
    *(float2*)(out + (size_t)m * 1000 + n) = make_float2(o0, o1);
}

// ---------------- HMMA GEMM ----------------------------------------------------
// C[M=512, Nout] = A[512,K] @ B[Npad,K]^T, bf16 in (integer-valued), fp32 accum.
// Tile 128x128x64, 3-stage cp.async pipeline, 8 warps (64x32 warp tiles).
constexpr int BM = 128, BN = 128, BK = 64, STAGES = 3, NTHREADS = 256;
constexpr int STAGE_BYTES = (BM * BK + BN * BK) * 2;   // 32768
constexpr int B_OFS = BM * BK * 2;                     // 16384

__global__ void __launch_bounds__(NTHREADS, 1)
gemm_q_kernel(const __nv_bfloat16* __restrict__ A,
              const __nv_bfloat16* __restrict__ B,
              const float* __restrict__ bias, float* __restrict__ out,
              int K, int Nout, int relu, int maxslot, int sa_slot, int sw_slot,
              int NK, int raw, int ostride) {
    extern __shared__ char smem_raw[];
    const uint32_t sb = smem_u32(smem_raw);

    const int tid = threadIdx.x;
    const int lane = tid & 31;
    const int wid = tid >> 5;
    const int wm = wid & 1;        // 2 m-blocks of 64
    const int wn = wid >> 1;       // 4 n-blocks of 32
    const int m0 = blockIdx.y * BM;
    const int n0 = blockIdx.x * BN;
    const size_t k_ofs = (size_t)blockIdx.z * NK * BK;
    float* outp = raw ? (out + (size_t)blockIdx.z * (512 * 1024)) : out;

    // ---- global->shared mapping: 2048 x 16B chunks / 256 threads = 8 each ----
    uint32_t s_st[8];
    const __nv_bfloat16* g_st[8];
#pragma unroll
    for (int i = 0; i < 8; i++) {
        int li = i * NTHREADS + tid;
        int isA = (li < 1024);
        int idx = li & 1023;
        int row = idx >> 3;            // 0..127
        int c = idx & 7;               // 16B chunk within 128B row
        s_st[i] = (uint32_t)((isA ? 0 : B_OFS) + row * 128 +
                             ((c ^ (row & 7)) << 4));
        g_st[i] = (isA ? (A + (size_t)(m0 + row) * K)
                       : (B + (size_t)(n0 + row) * K)) + k_ofs + c * 8;
    }

    // prologue loads
#pragma unroll
    for (int st = 0; st < 2; st++) {
        if (st < NK) {
            uint32_t base = sb + (uint32_t)(st % STAGES) * STAGE_BYTES;
#pragma unroll
            for (int i = 0; i < 8; i++)
                cp_async16(base + s_st[i], g_st[i] + (size_t)st * BK);
            CP_COMMIT();
        }
    }

    // ---- ldmatrix per-lane base addresses (within stage) ----
    const int r = lane & 7;
    const int g = lane >> 3;
    uint32_t a_row[4];
    int a_rx[4];
#pragma unroll
    for (int mi = 0; mi < 4; mi++) {
        int row = wm * 64 + mi * 16 + (g & 1) * 8 + r;
        a_row[mi] = (uint32_t)(row * 128);
        a_rx[mi] = row & 7;
    }
    uint32_t b_row[2];
    int b_rx[2];
#pragma unroll
    for (int p = 0; p < 2; p++) {
        int row = wn * 32 + p * 16 + (g >> 1) * 8 + r;
        b_row[p] = (uint32_t)(B_OFS + row * 128);
        b_rx[p] = row & 7;
    }

    float acc[4][4][4];
#pragma unroll
    for (int mi = 0; mi < 4; mi++)
#pragma unroll
        for (int ni = 0; ni < 4; ni++)
#pragma unroll
            for (int e = 0; e < 4; e++) acc[mi][ni][e] = 0.0f;

#pragma unroll 1
    for (int kc = 0; kc < NK; kc++) {
        if (kc + 2 < NK) {
            uint32_t base = sb + (uint32_t)((kc + 2) % STAGES) * STAGE_BYTES;
#pragma unroll
            for (int i = 0; i < 8; i++)
                cp_async16(base + s_st[i], g_st[i] + (size_t)(kc + 2) * BK);
            CP_COMMIT();
        }
        int rem = NK - 1 - kc;
        if (rem >= 2)      asm volatile("cp.async.wait_group 2;" ::: "memory");
        else if (rem == 1) asm volatile("cp.async.wait_group 1;" ::: "memory");
        else               asm volatile("cp.async.wait_group 0;" ::: "memory");
        __syncthreads();

        const uint32_t stage = sb + (uint32_t)(kc % STAGES) * STAGE_BYTES;
#pragma unroll
        for (int s = 0; s < 4; s++) {
            uint32_t af[4][4];
#pragma unroll
            for (int mi = 0; mi < 4; mi++) {
                int chunk = 2 * s + (g >> 1);
                LDSM4(af[mi], stage + a_row[mi] +
                              (uint32_t)((chunk ^ a_rx[mi]) << 4));
            }
            uint32_t bf[2][4];
#pragma unroll
            for (int p = 0; p < 2; p++) {
                int chunk = 2 * s + (g & 1);
                LDSM4(bf[p], stage + b_row[p] +
                             (uint32_t)((chunk ^ b_rx[p]) << 4));
            }
#pragma unroll
            for (int mi = 0; mi < 4; mi++) {
#pragma unroll
                for (int p = 0; p < 2; p++) {
                    MMA16816(acc[mi][2 * p],     af[mi], bf[p][0], bf[p][1]);
                    MMA16816(acc[mi][2 * p + 1], af[mi], bf[p][2], bf[p][3]);
                }
            }
        }
        __syncthreads();
    }

    // ---- epilogue ----
    if (raw) {
#pragma unroll
        for (int mi = 0; mi < 4; mi++) {
#pragma unroll
            for (int half = 0; half < 2; half++) {
                int m = m0 + wm * 64 + mi * 16 + (lane >> 2) + half * 8;
#pragma unroll
                for (int ni = 0; ni < 4; ni++) {
                    int n = n0 + wn * 32 + ni * 8 + (lane & 3) * 2;
                    *(float2*)(outp + (size_t)m * ostride + n) =
                        make_float2(acc[mi][ni][half * 2 + 0],
                                    acc[mi][ni][half * 2 + 1]);
                }
            }
        }
        return;
    }

    const float sa = g_maxes[sa_slot] / NLV;
    const float sw = g_maxes[sw_slot] / NLV;
    const float bs = sa * sw;
    float lmax = 0.0f;

    float bq[4][2];
#pragma unroll
    for (int ni = 0; ni < 4; ni++) {
        int n = n0 + wn * 32 + ni * 8 + (lane & 3) * 2;
#pragma unroll
        for (int e = 0; e < 2; e++)
            bq[ni][e] = (n + e < Nout) ? rintf(bias[n + e] / bs) * bs : 0.0f;
    }

#pragma unroll
    for (int mi = 0; mi < 4; mi++) {
#pragma unroll
        for (int half = 0; half < 2; half++) {
            int m = m0 + wm * 64 + mi * 16 + (lane >> 2) + half * 8;
#pragma unroll
            for (int ni = 0; ni < 4; ni++) {
                int n = n0 + wn * 32 + ni * 8 + (lane & 3) * 2;
                if (n < Nout) {
                    float v0 = acc[mi][ni][half * 2 + 0] * bs + bq[ni][0];
                    float v1 = acc[mi][ni][half * 2 + 1] * bs + bq[ni][1];
                    if (relu) { v0 = fmaxf(v0, 0.0f); v1 = fmaxf(v1, 0.0f); }
                    *(float2*)(outp + (size_t)m * ostride + n) =
                        make_float2(v0, v1);
                    lmax = fmaxf(lmax, fmaxf(fabsf(v0), fabsf(v1)));
                }
            }
        }
    }
    if (maxslot >= 0) {
#pragma unroll
        for (int o = 16; o; o >>= 1)
            lmax = fmaxf(lmax, __shfl_xor_sync(0xFFFFFFFFu, lmax, o));
        if (lane == 0)
            atomicMax((unsigned int*)&g_maxes[maxslot], __float_as_uint(lmax));
    }
}

// ---------------- launch -------------------------------------------------------
extern "C" void kernel_launch(void* const* d_in, const int* in_sizes, int n_in,
                              void* d_out, int out_size) {
    const float* x  = (const float*)d_in[0];
    const float* w1 = (const float*)d_in[1];
    const float* b1 = (const float*)d_in[2];
    const float* w2 = (const float*)d_in[3];
    const float* b2 = (const float*)d_in[4];
    const float* w3 = (const float*)d_in[5];
    const float* b3 = (const float*)d_in[6];
    float* out = (float*)d_out;

    void *p_xq, *p_w1q, *p_w2q, *p_w3q, *p_h, *p_hq, *p_part;
    cudaGetSymbolAddress(&p_xq, g_xq);
    cudaGetSymbolAddress(&p_w1q, g_w1q);
    cudaGetSymbolAddress(&p_w2q, g_w2q);
    cudaGetSymbolAddress(&p_w3q, g_w3q);
    cudaGetSymbolAddress(&p_h, g_h);
    cudaGetSymbolAddress(&p_hq, g_hq);
    cudaGetSymbolAddress(&p_part, g_part);

    const int SMEM = STAGES * STAGE_BYTES;   // 98304
    cudaFuncSetAttribute(gemm_q_kernel,
                         cudaFuncAttributeMaxDynamicSharedMemorySize, SMEM);

    const int RB = 1184;  // 8 * 148 SMs, grid-stride

    cudaStream_t s1;
    cudaStreamCreateWithFlags(&s1, cudaStreamNonBlocking);
    cudaEvent_t e_init, e_x, e_w1, e_aux;
    cudaEventCreateWithFlags(&e_init, cudaEventDisableTiming);
    cudaEventCreateWithFlags(&e_x, cudaEventDisableTiming);
    cudaEventCreateWithFlags(&e_w1, cudaEventDisableTiming);
    cudaEventCreateWithFlags(&e_aux, cudaEventDisableTiming);

    // launch #0
    init_maxes_kernel<<<1, 32>>>();
    cudaEventRecord(e_init, 0);

    // s0 critical path: w1 aux (launches #1, #2)
    maxabs_kernel<<<RB, 256>>>(w1, (4096 * 9216) / 4, 1);
    quant_kernel<<<RB, 256>>>(w1, (__nv_bfloat16*)p_w1q,
                              (4096 * 9216) / 4, (4096 * 9216) / 4, 1, -127.0f);
    cudaEventRecord(e_w1, 0);

    // s1: x aux concurrent with w1 aux (launches #3, #4)
    cudaStreamWaitEvent(s1, e_init, 0);
    maxabs_kernel<<<RB, 256, 0, s1>>>(x, (512 * 9216) / 4, 0);
    quant_kernel<<<RB, 256, 0, s1>>>(x, (__nv_bfloat16*)p_xq,
                                     (512 * 9216) / 4, (512 * 9216) / 4, 0,
                                     -128.0f);
    cudaEventRecord(e_x, s1);

    // GEMM1 (launch #5 -> ncu -s 5 -c 1 captures this)
    cudaStreamWaitEvent(0, e_x, 0);
    gemm_q_kernel<<<dim3(32, 4, 1), NTHREADS, SMEM>>>(
        (const __nv_bfloat16*)p_xq, (const __nv_bfloat16*)p_w1q, b1,
        (float*)p_h, 9216, 4096, 1, 4, 0, 1, 9216 / 64, 0, 4096);

    // s1: w2/w3 aux under GEMM1 (starts when GEMM1 can start)
    cudaStreamWaitEvent(s1, e_w1, 0);
    maxabs_kernel<<<RB, 256, 0, s1>>>(w2, (4096 * 4096) / 4, 2);
    quant_kernel<<<RB, 256, 0, s1>>>(w2, (__nv_bfloat16*)p_w2q,
                                     (4096 * 4096) / 4, (4096 * 4096) / 4, 2,
                                     -127.0f);
    maxabs_kernel<<<RB, 256, 0, s1>>>(w3, (1000 * 4096) / 4, 3);
    quant_kernel<<<RB, 256, 0, s1>>>(w3, (__nv_bfloat16*)p_w3q,
                                     (1000 * 4096) / 4, (1024 * 4096) / 4, 3,
                                     -127.0f);
    cudaEventRecord(e_aux, s1);

    quant_kernel<<<RB, 256>>>((const float*)p_h, (__nv_bfloat16*)p_hq,
                              (512 * 4096) / 4, (512 * 4096) / 4, 4, -128.0f);

    // GEMM2 needs w2q (and downstream GEMM3 needs w3q)
    cudaStreamWaitEvent(0, e_aux, 0);
    gemm_q_kernel<<<dim3(32, 4, 1), NTHREADS, SMEM>>>(
        (const __nv_bfloat16*)p_hq, (const __nv_bfloat16*)p_w2q, b2,
        (float*)p_h, 4096, 4096, 1, 5, 4, 2, 4096 / 64, 0, 4096);
    quant_kernel<<<RB, 256>>>((const float*)p_h, (__nv_bfloat16*)p_hq,
                              (512 * 4096) / 4, (512 * 4096) / 4, 5, -128.0f);

    // Layer 3: split-K=4 raw partials (8x4x4 = 128 CTAs), then reduce
    gemm_q_kernel<<<dim3(8, 4, 4), NTHREADS, SMEM>>>(
        (const __nv_bfloat16*)p_hq, (const __nv_bfloat16*)p_w3q, b3,
        (float*)p_part, 4096, 1024, 0, -1, 5, 3, (4096 / 64) / 4, 1, 1024);
    reduce3_kernel<<<(512 * 500 + 255) / 256, 256>>>(b3, out);

    cudaEventDestroy(e_init);
    cudaEventDestroy(e_x);
    cudaEventDestroy(e_w1);
    cudaEventDestroy(e_aux);
    cudaStreamDestroy(s1);
}